// round 4
// baseline (speedup 1.0000x reference)
#include <cuda_runtime.h>
#include <cuda_bf16.h>
#include <cstdint>

// DepthToSpace: x [B=8, C=64, H=256, W=256] fp32 -> out [8, 4, 1024, 1024] fp32
// S=4 groups, cell=4. out[b, s, 4h+r, 4w+c] = x[b, 16s+4r+c, h, w].
//
// Vectorized plan: each thread owns 16 consecutive output floats in one output
// row (4 float4 stores, 64B contiguous per thread). It loads one float4 from
// each of the 4 channels c=0..3 (same (h, w4) coordinates, channel stride
// 64KB floats), transposes 4x4 in registers, and writes the interleaved
// result. All loads and stores are 128-bit and warp-coalesced.

static constexpr int W4_PER_ROW = 64;   // 256 input cols / 4 per float4
static constexpr int OROWS      = 1024; // output rows per (b,s)
static constexpr int NBS        = 32;   // B*S = 8*4

__global__ __launch_bounds__(256, 8)
void depth_to_space_kernel(const float4* __restrict__ x4,
                           float4* __restrict__ out4)
{
    const unsigned t = blockIdx.x * blockDim.x + threadIdx.x;
    // t in [0, NBS * OROWS * W4_PER_ROW) = [0, 2097152)
    const unsigned w4   = t & (W4_PER_ROW - 1);        // 0..63
    const unsigned orow = (t >> 6) & (OROWS - 1);      // 0..1023
    const unsigned bs   = t >> 16;                     // 0..31

    const unsigned h = orow >> 2;   // input spatial row
    const unsigned r = orow & 3;    // intra-cell row

    // channel base = b*64 + s*16 + r*4 = bs*16 + r*4  (since b*64 + s*16 = (b*4+s)*16 = bs*16)
    const unsigned ch0 = bs * 16 + r * 4;

    // input float4 index for channel (ch0 + c): ((ch0+c)*256 + h)*64 + w4
    const size_t in_base = ((size_t)ch0 * 256u + h) * 64u + w4;
    const size_t ch_stride = 256u * 64u;  // one channel in float4 units (16384)

    float4 v0 = x4[in_base];
    float4 v1 = x4[in_base + ch_stride];
    float4 v2 = x4[in_base + 2 * ch_stride];
    float4 v3 = x4[in_base + 3 * ch_stride];

    // output float4 base: ((bs*1024 + orow) * 1024 + w4*16) / 4
    const size_t ob = ((size_t)bs * OROWS + orow) * 256u + (size_t)w4 * 4u;

    out4[ob + 0] = make_float4(v0.x, v1.x, v2.x, v3.x);
    out4[ob + 1] = make_float4(v0.y, v1.y, v2.y, v3.y);
    out4[ob + 2] = make_float4(v0.z, v1.z, v2.z, v3.z);
    out4[ob + 3] = make_float4(v0.w, v1.w, v2.w, v3.w);
}

extern "C" void kernel_launch(void* const* d_in, const int* in_sizes, int n_in,
                              void* d_out, int out_size)
{
    const float4* x4  = (const float4*)d_in[0];
    float4*       o4  = (float4*)d_out;

    // total threads = 8*4 * 1024 * 64 = 2,097,152
    const int threads = 256;
    const int blocks  = (NBS * OROWS * W4_PER_ROW) / threads;  // 8192
    depth_to_space_kernel<<<blocks, threads>>>(x4, o4);
}

// round 5
// speedup vs baseline: 1.1065x; 1.1065x over previous
#include <cuda_runtime.h>
#include <cuda_bf16.h>
#include <cstdint>

// DepthToSpace: x [8, 64, 256, 256] fp32 -> out [8, 4, 1024, 1024] fp32
// out[b, s, 4h+r, 4w+c] = x[b, 16s+4r+c, h, w]
//
// Store-coalesced formulation: output float4 #ofi (covering out cols
// 4*ofi..4*ofi+3 of one output row) equals
//   { x[ch0][h][ofi], x[ch0+1][h][ofi], x[ch0+2][h][ofi], x[ch0+3][h][ofi] }
// with w = ofi a SCALAR input column. So:
//   - stores: consecutive lanes -> consecutive float4  => fully coalesced STG.128
//   - loads:  consecutive lanes -> consecutive 4B scalars per channel
//             => fully coalesced 128B LDG.32 wavefronts
// Each warp covers 128 consecutive output float4s (half an output row);
// each thread produces 4 of them at lane-stride 32 (MLP = 16 scalar loads).

__global__ __launch_bounds__(256, 8)
void depth_to_space_kernel(const float* __restrict__ x,
                           float4* __restrict__ out4)
{
    const unsigned t    = blockIdx.x * blockDim.x + threadIdx.x;  // 0 .. 2097151
    const unsigned lane = t & 31;
    const unsigned wid  = t >> 5;                                 // 0 .. 65535

    // This warp covers output-float4 indices [wid*128, wid*128+128).
    // 256 float4 per output row -> orow/bs constant across the warp.
    const unsigned ofi_base = wid * 128;
    const unsigned orow = (ofi_base >> 8) & 1023;   // output row within (b,s)
    const unsigned bs   =  ofi_base >> 18;          // b*4 + s, 0..31

    const unsigned h   = orow >> 2;                 // input spatial row
    const unsigned r   = orow & 3;                  // intra-cell row
    const unsigned ch0 = bs * 16 + r * 4;           // first of 4 input channels

    // Scalar input base for channel ch0 at (h, w=0): (ch0*256 + h)*256
    const size_t in_row  = ((size_t)ch0 << 16) + ((size_t)h << 8);
    const unsigned w0    = ((wid & 1) << 7) + lane; // column for k=0
    const size_t CH      = 1u << 16;                // channel stride (floats)

    float v[4][4];
    #pragma unroll
    for (int k = 0; k < 4; k++) {
        const size_t a = in_row + w0 + 32u * k;
        #pragma unroll
        for (int c = 0; c < 4; c++)
            v[k][c] = x[a + (size_t)c * CH];
    }

    const size_t ob = (size_t)ofi_base + w0 - ((wid & 1) << 7); // = ofi_base + lane
    #pragma unroll
    for (int k = 0; k < 4; k++)
        out4[ob + 32u * k] = make_float4(v[k][0], v[k][1], v[k][2], v[k][3]);
}

extern "C" void kernel_launch(void* const* d_in, const int* in_sizes, int n_in,
                              void* d_out, int out_size)
{
    const float* x  = (const float*)d_in[0];
    float4*      o4 = (float4*)d_out;

    // 8,388,608 output float4s / 4 per thread = 2,097,152 threads
    const int threads = 256;
    const int blocks  = 8192;
    depth_to_space_kernel<<<blocks, threads>>>(x, o4);
}

// round 6
// speedup vs baseline: 1.1112x; 1.0043x over previous
#include <cuda_runtime.h>
#include <cuda_bf16.h>
#include <cstdint>

// DepthToSpace: x [8, 64, 256, 256] fp32 -> out [8, 4, 1024, 1024] fp32
// out[b, s, 4h+r, 4w+c] = x[b, 16s+4r+c, h, w]
//
// Store-coalesced formulation (R4), retuned for memory-level parallelism:
// each thread produces 2 output float4s (8 scalar loads front-batched, then
// 2 STG.128). Small body => ptxas keeps all 8 loads live in registers and
// issues them back-to-back (MLP=8/thread, no store-stall bubbles between
// load batches), unlike the R4 16-load body that got pipelined at MLP~4.
//
//   - stores: consecutive lanes -> consecutive float4  => coalesced STG.128
//   - loads:  consecutive lanes -> consecutive 4B per channel => 128B wavefronts

__global__ __launch_bounds__(256, 8)
void depth_to_space_kernel(const float* __restrict__ x,
                           float4* __restrict__ out4)
{
    const unsigned t    = blockIdx.x * blockDim.x + threadIdx.x;  // 0 .. 4194303
    const unsigned lane = t & 31;
    const unsigned wid  = t >> 5;                                 // 0 .. 131071

    // This warp covers output-float4 indices [wid*64, wid*64+64).
    // 256 float4 per output row, 64 | 256 -> orow/bs constant across warp.
    const unsigned ofi_base = wid * 64;
    const unsigned orow = (ofi_base >> 8) & 1023;   // output row within (b,s)
    const unsigned bs   =  ofi_base >> 18;          // b*4 + s, 0..31

    const unsigned h   = orow >> 2;                 // input spatial row
    const unsigned r   = orow & 3;                  // intra-cell row
    const unsigned ch0 = bs * 16 + r * 4;           // first of 4 input channels

    // Scalar input address for channel ch0, row h, col w0:
    const unsigned w0     = (ofi_base & 255) + lane;       // col for k=0
    const unsigned in_a   = (ch0 << 16) + (h << 8) + w0;   // fits in 32 bits (max 2^24)
    const unsigned CH     = 1u << 16;                      // channel stride (floats)

    float v[2][4];
    #pragma unroll
    for (int k = 0; k < 2; k++) {
        const unsigned a = in_a + 32u * k;
        #pragma unroll
        for (int c = 0; c < 4; c++)
            v[k][c] = x[a + c * CH];
    }

    const unsigned ob = ofi_base + lane;
    #pragma unroll
    for (int k = 0; k < 2; k++)
        out4[ob + 32u * k] = make_float4(v[k][0], v[k][1], v[k][2], v[k][3]);
}

extern "C" void kernel_launch(void* const* d_in, const int* in_sizes, int n_in,
                              void* d_out, int out_size)
{
    const float* x  = (const float*)d_in[0];
    float4*      o4 = (float4*)d_out;

    // 8,388,608 output float4s / 2 per thread = 4,194,304 threads
    const int threads = 256;
    const int blocks  = 16384;
    depth_to_space_kernel<<<blocks, threads>>>(x, o4);
}